// round 14
// baseline (speedup 1.0000x reference)
#include <cuda_runtime.h>
#include <cstdint>

#define B_   8
#define CIN  96
#define CMID 48
#define HH   256
#define WW   256
#define H2   128
#define W2   128
#define CO   192

// conv1 output y in fp16: [b][oc][h][w], stored as half2 (adjacent pixels). 50 MB.
__device__ unsigned g_yh[B_ * CMID * HH * WW / 2];
// Pre-packed fp16 weights: [chunk6][tap9][icp8][oc48] half2 (lo = even ic)
__device__ unsigned g_wph[6 * 9 * 8 * 48];
// Pre-packed, pre-padded fp16 x: [b][icp48][row 258][col 264] half2. ~105 MB.
#define XPR 258
#define XPC 264
__device__ unsigned g_xh[B_ * 48 * XPR * XPC];

__device__ __forceinline__ unsigned pack_h2(float lo, float hi) {
    unsigned r;
    asm("{ .reg .b16 l, h; cvt.rn.f16.f32 l, %1; cvt.rn.f16.f32 h, %2; "
        "mov.b32 %0, {l, h}; }" : "=r"(r) : "f"(lo), "f"(hi));
    return r;
}
__device__ __forceinline__ float2 h2f2(unsigned h) {
    float2 f;
    asm("{ .reg .b16 l, h; mov.b32 {l, h}, %2; "
        "cvt.f32.f16 %0, l; cvt.f32.f16 %1, h; }"
        : "=f"(f.x), "=f"(f.y) : "r"(h));
    return f;
}

__device__ __forceinline__ void mma_f16(float* c,
    unsigned a0, unsigned a1, unsigned a2, unsigned a3,
    unsigned b0, unsigned b1)
{
    asm volatile(
        "mma.sync.aligned.m16n8k16.row.col.f32.f16.f16.f32 "
        "{%0,%1,%2,%3}, {%4,%5,%6,%7}, {%8,%9}, {%0,%1,%2,%3};"
        : "+f"(c[0]), "+f"(c[1]), "+f"(c[2]), "+f"(c[3])
        : "r"(a0), "r"(a1), "r"(a2), "r"(a3), "r"(b0), "r"(b1));
}

__device__ __forceinline__ uint32_t smem_u32(const void* p) {
    uint32_t a;
    asm("{ .reg .u64 t; cvta.to.shared.u64 t, %1; cvt.u32.u64 %0, t; }"
        : "=r"(a) : "l"(p));
    return a;
}
#define CP_ASYNC16(dst, src) \
    asm volatile("cp.async.cg.shared.global [%0], [%1], 16;" \
                 :: "r"(dst), "l"(src))
#define CP_COMMIT() asm volatile("cp.async.commit_group;" ::: "memory")
#define CP_WAIT1()  asm volatile("cp.async.wait_group 1;" ::: "memory")
#define CP_WAIT0()  asm volatile("cp.async.wait_group 0;" ::: "memory")

// ---------------------------------------------------------------------------
// Fused prepass: weights then x relayout. (unchanged, ~46us, DRAM floor)
// ---------------------------------------------------------------------------
#define WN   (6 * 9 * 8 * 48)
#define PX_N (B_ * 48 * XPR * (XPC / 4))

__global__ void prep_kernel(const float* __restrict__ x,
                            const float* __restrict__ w)
{
    int i = blockIdx.x * 256 + threadIdx.x;
    if (i < WN) {
        int chunk = i / 3456;
        int r  = i % 3456;
        int tap = r / 384;
        int r2  = r % 384;
        int icp = r2 / 48;
        int oc  = r2 % 48;
        int ic  = chunk * 16 + icp * 2;
        g_wph[i] = pack_h2(w[(oc * 96 + ic) * 9 + tap],
                           w[(oc * 96 + ic + 1) * 9 + tap]);
        return;
    }
    i -= WN;
    if (i >= PX_N) return;
    int pc0 = (i % (XPC / 4)) * 4;
    int t   = i / (XPC / 4);
    int pr  = t % XPR;
    int t2  = t / XPR;
    int icp = t2 % 48;
    int b   = t2 / 48;
    int gr  = pr - 1;
    const float* s0 = x + ((size_t)((b * CIN + icp * 2) * HH + gr)) * WW;
    const float* s1 = s0 + (size_t)HH * WW;
    bool rok = ((unsigned)gr < (unsigned)HH);
    unsigned res[4];
    #pragma unroll
    for (int j = 0; j < 4; j++) {
        int ww = pc0 + j - 1;
        bool ok = rok && ((unsigned)ww < (unsigned)WW);
        float f0 = ok ? s0[ww] : 0.f;
        float f1 = ok ? s1[ww] : 0.f;
        res[j] = pack_h2(f0, f1);
    }
    *(uint4*)&g_xh[((size_t)(b * 48 + icp) * XPR + pr) * XPC + pc0] =
        *(uint4*)res;
}

// ---------------------------------------------------------------------------
// conv1 via mma.sync fp16 m16n8k16, cp.async double-buffered. (R12 exact)
// ---------------------------------------------------------------------------
#define XS_WORDS (8 * 6 * 132)   // 6336
#define WS_WORDS (9 * 8 * 56)    // 4032
#define SMEM_SZ  ((2 * XS_WORDS + 2 * WS_WORDS) * 4)

__global__ __launch_bounds__(256, 2) void conv1_mma_kernel()
{
    extern __shared__ unsigned sm[];
    unsigned* xs0 = sm;
    unsigned* ws0 = sm + 2 * XS_WORDS;

    const int tid  = threadIdx.x;
    const int lane = tid & 31;
    const int wid  = tid >> 5;
    const int g    = lane >> 2;
    const int u    = lane & 3;

    const int w0 = blockIdx.x * 128;
    const int h0 = blockIdx.y * 4;
    const int b  = blockIdx.z;

    const int wrow  = wid >> 1;
    const int wcolb = (wid & 1) * 64;

    const uint32_t xs_sm = smem_u32(xs0);
    const uint32_t ws_sm = smem_u32(ws0);

    auto issue = [&](int chunk, int buf) {
        const unsigned* srcp =
            g_xh + ((size_t)(b * 48 + chunk * 8 + wid) * XPR + h0) * XPC + w0;
        uint32_t xd = xs_sm + (buf * XS_WORDS + wid * (6 * 132)) * 4;
        for (int j = lane; j < 198; j += 32) {
            int r = j / 33, q = j - r * 33;
            CP_ASYNC16(xd + (r * 132 + q * 4) * 4,
                       srcp + (size_t)r * XPC + q * 4);
        }
        const unsigned* wsrc = g_wph + chunk * 3456;
        uint32_t wd = ws_sm + buf * WS_WORDS * 4;
        for (int j = lane; j < 108; j += 32) {
            int rr = wid * 9 + j / 12, q = j % 12;
            CP_ASYNC16(wd + (rr * 56 + q * 4) * 4, wsrc + rr * 48 + q * 4);
        }
    };

    float acc[4][6][4];
    #pragma unroll
    for (int t = 0; t < 4; t++)
        #pragma unroll
        for (int n = 0; n < 6; n++)
            #pragma unroll
            for (int k = 0; k < 4; k++)
                acc[t][n][k] = 0.f;

    issue(0, 0);
    CP_COMMIT();

    for (int chunk = 0; chunk < 6; chunk++) {
        const int buf = chunk & 1;
        if (chunk < 5) {
            issue(chunk + 1, buf ^ 1);
            CP_COMMIT();
            CP_WAIT1();
        } else {
            CP_WAIT0();
        }
        __syncthreads();

        const unsigned* xsb = xs0 + buf * XS_WORDS;
        const unsigned* wsb = ws0 + buf * WS_WORDS;

        #pragma unroll
        for (int tap = 0; tap < 9; tap++) {
            const int kh = tap / 3, kw = tap % 3;
            const int xr = wrow + kh;

            unsigned bf[6][2];
            #pragma unroll
            for (int n = 0; n < 6; n++) {
                bf[n][0] = wsb[(tap * 8 + u) * 56 + n * 8 + g];
                bf[n][1] = wsb[(tap * 8 + u + 4) * 56 + n * 8 + g];
            }
            #pragma unroll
            for (int t = 0; t < 4; t++) {
                const int colc = wcolb + t * 16 + g + kw;
                unsigned a0 = xsb[(u * 6 + xr) * 132 + colc];
                unsigned a1 = xsb[(u * 6 + xr) * 132 + colc + 8];
                unsigned a2 = xsb[((u + 4) * 6 + xr) * 132 + colc];
                unsigned a3 = xsb[((u + 4) * 6 + xr) * 132 + colc + 8];
                #pragma unroll
                for (int n = 0; n < 6; n++)
                    mma_f16(acc[t][n], a0, a1, a2, a3, bf[n][0], bf[n][1]);
            }
        }
        __syncthreads();
    }

    #pragma unroll
    for (int t = 0; t < 4; t++) {
        const int p0 = wid * 64 + t * 16 + g;
        const int h  = h0 + (p0 >> 7);
        const int hc = ((w0 + (p0 & 127)) >> 1);
        #pragma unroll
        for (int n = 0; n < 6; n++) {
            const int oc = n * 8 + 2 * u;
            float q0 = __shfl_xor_sync(0xffffffffu, acc[t][n][0], 4);
            float q1 = __shfl_xor_sync(0xffffffffu, acc[t][n][1], 4);
            float q2 = __shfl_xor_sync(0xffffffffu, acc[t][n][2], 4);
            float q3 = __shfl_xor_sync(0xffffffffu, acc[t][n][3], 4);
            if (!(g & 1)) {
                unsigned* base =
                    g_yh + ((size_t)(b * CMID + oc) * HH + h) * 128 + hc;
                base[0]                       = pack_h2(acc[t][n][0], q0);
                base[(size_t)HH * WW / 2]     = pack_h2(acc[t][n][1], q1);
                base[4]                       = pack_h2(acc[t][n][2], q2);
                base[(size_t)HH * WW / 2 + 4] = pack_h2(acc[t][n][3], q3);
            }
        }
    }
}

// ---------------------------------------------------------------------------
// conv2 v5 (fixed): TWO y-channels per CTA sharing one mask tile.
// CTA: 16 out rows x 128 cols x {c0, c0+1} x dy. Thread: 2 rows x 4 cols
// x 2 dx x 2 ch = 16 outputs. grid (8, 48, 8) = 3072 CTAs.
// ---------------------------------------------------------------------------
__global__ __launch_bounds__(256) void conv2_kernel(
    const float* __restrict__ mask, const float* __restrict__ wp,
    float* __restrict__ out)
{
    __shared__ __align__(16) float sy[2][2][18][132];   // [ch][parity][r][col]
    __shared__ __align__(16) float smm[2][18][132];     // [parity][r][col]
    __shared__ float swp[2][36];

    const int tid = threadIdx.x;
    const int hb  = blockIdx.x * 16;
    const int dy  = blockIdx.y & 1;
    const int c0  = (blockIdx.y >> 1) * 2;
    const int b   = blockIdx.z;

    if (tid < 72) swp[tid / 36][tid % 36] =
        wp[(4 * (c0 + tid / 36) + 2 * dy) * 18 + (tid % 36)];

    // ---- stage y for both channels: 2304 slots = 2 ch x 1152 (r, q2) ----
    #pragma unroll
    for (int it = 0; it < 9; it++) {
        int idx = it * 256 + tid;
        // idx in [0, 2304)
        int ch  = idx / 1152;
        int rem = idx - ch * 1152;
        int r   = rem >> 6;
        int q2  = (rem & 63) * 2;
        int gy  = 2 * (hb - 1 + r) + dy;
        uint2 yv = make_uint2(0u, 0u);
        if ((unsigned)gy < (unsigned)HH)
            yv = *(const uint2*)
                &g_yh[((size_t)(b * CMID + c0 + ch) * HH + gy) * 128 + q2];
        float2 f0 = h2f2(yv.x), f1 = h2f2(yv.y);
        sy[ch][0][r][1 + q2] = f0.x;  sy[ch][1][r][1 + q2] = f0.y;
        sy[ch][0][r][2 + q2] = f1.x;  sy[ch][1][r][2 + q2] = f1.y;
    }
    // ---- stage mask once: 1152 slots ----
    for (int idx = tid; idx < 1152; idx += 256) {
        int r  = idx >> 6;
        int q2 = (idx & 63) * 2;
        int gy = 2 * (hb - 1 + r) + dy;
        float4 mv = make_float4(0.f, 0.f, 0.f, 0.f);
        if ((unsigned)gy < (unsigned)HH)
            mv = *(const float4*)&mask[((size_t)(b * HH) + gy) * WW + 2 * q2];
        smm[0][r][1 + q2] = mv.x; smm[1][r][1 + q2] = mv.y;
        smm[0][r][2 + q2] = mv.z; smm[1][r][2 + q2] = mv.w;
    }
    if (tid < 18) {
        sy[0][0][tid][0] = 0.f;   sy[0][1][tid][0] = 0.f;
        sy[0][0][tid][129] = 0.f; sy[0][1][tid][129] = 0.f;
        sy[1][0][tid][0] = 0.f;   sy[1][1][tid][0] = 0.f;
        sy[1][0][tid][129] = 0.f; sy[1][1][tid][129] = 0.f;
        smm[0][tid][0] = 0.f;     smm[1][tid][0] = 0.f;
        smm[0][tid][129] = 0.f;   smm[1][tid][129] = 0.f;
    }
    __syncthreads();

    const int rr  = tid >> 5;
    const int w0c = (tid & 31) * 4;

    // acc[ch][orow][dx][p]
    float a[2][2][2][4];
    #pragma unroll
    for (int ch = 0; ch < 2; ch++)
        #pragma unroll
        for (int o = 0; o < 2; o++)
            #pragma unroll
            for (int gx = 0; gx < 2; gx++)
                #pragma unroll
                for (int p = 0; p < 4; p++)
                    a[ch][o][gx][p] = 0.f;

    #pragma unroll
    for (int r = 0; r < 4; r++) {
        const int sr = 2 * rr + r;
        // mask windows (shared by both channels)
        float4 ma0 = *(const float4*)&smm[0][sr][w0c];
        float2 mb0 = *(const float2*)&smm[0][sr][w0c + 4];
        float4 ma1 = *(const float4*)&smm[1][sr][w0c];
        float2 mb1 = *(const float2*)&smm[1][sr][w0c + 4];
        float mv0[6] = {ma0.x, ma0.y, ma0.z, ma0.w, mb0.x, mb0.y};
        float mv1[6] = {ma1.x, ma1.y, ma1.z, ma1.w, mb1.x, mb1.y};

        #pragma unroll
        for (int ch = 0; ch < 2; ch++) {
            float4 ya0 = *(const float4*)&sy[ch][0][sr][w0c];
            float2 yb0 = *(const float2*)&sy[ch][0][sr][w0c + 4];
            float4 ya1 = *(const float4*)&sy[ch][1][sr][w0c];
            float2 yb1 = *(const float2*)&sy[ch][1][sr][w0c + 4];
            float yv0[6] = {ya0.x, ya0.y, ya0.z, ya0.w, yb0.x, yb0.y};
            float yv1[6] = {ya1.x, ya1.y, ya1.z, ya1.w, yb1.x, yb1.y};

            #pragma unroll
            for (int orow = 0; orow < 2; orow++) {
                const int kh = r - orow;
                if (kh < 0 || kh > 2) continue;
                #pragma unroll
                for (int kw = 0; kw < 3; kw++) {
                    float wy0 = swp[ch][kh * 3 + kw];
                    float wm0 = swp[ch][9 + kh * 3 + kw];
                    float wy1 = swp[ch][18 + kh * 3 + kw];
                    float wm1 = swp[ch][27 + kh * 3 + kw];
                    #pragma unroll
                    for (int p = 0; p < 4; p++) {
                        a[ch][orow][0][p] =
                            fmaf(wy0, yv0[kw + p], a[ch][orow][0][p]);
                        a[ch][orow][0][p] =
                            fmaf(wm0, mv0[kw + p], a[ch][orow][0][p]);
                        a[ch][orow][1][p] =
                            fmaf(wy1, yv1[kw + p], a[ch][orow][1][p]);
                        a[ch][orow][1][p] =
                            fmaf(wm1, mv1[kw + p], a[ch][orow][1][p]);
                    }
                }
            }
        }
    }

    #pragma unroll
    for (int ch = 0; ch < 2; ch++) {
        const int g0 = 4 * (c0 + ch) + 2 * dy;
        #pragma unroll
        for (int orow = 0; orow < 2; orow++) {
            const int h = hb + 2 * rr + orow;
            *(float4*)&out[((size_t)(b * CO + g0) * H2 + h) * W2 + w0c] =
                make_float4(a[ch][orow][0][0], a[ch][orow][0][1],
                            a[ch][orow][0][2], a[ch][orow][0][3]);
            *(float4*)&out[((size_t)(b * CO + g0 + 1) * H2 + h) * W2 + w0c] =
                make_float4(a[ch][orow][1][0], a[ch][orow][1][1],
                            a[ch][orow][1][2], a[ch][orow][1][3]);
        }
    }
}

// ---------------------------------------------------------------------------
extern "C" void kernel_launch(void* const* d_in, const int* in_sizes, int n_in,
                              void* d_out, int out_size)
{
    const float* x      = (const float*)d_in[0];
    const float* mask   = (const float*)d_in[1];
    const float* w_body = (const float*)d_in[2];
    const float* w_proj = (const float*)d_in[3];
    float* out = (float*)d_out;

    cudaFuncSetAttribute(conv1_mma_kernel,
                         cudaFuncAttributeMaxDynamicSharedMemorySize, SMEM_SZ);

    prep_kernel<<<(WN + PX_N + 255) / 256, 256>>>(x, w_body);

    dim3 g1(WW / 128, HH / 4, B_);      // (2, 64, 8) = 1024 CTAs
    conv1_mma_kernel<<<g1, 256, SMEM_SZ>>>();

    dim3 g2(H2 / 16, 48, B_);           // (8, 48, 8) = 3072 CTAs
    conv2_kernel<<<g2, 256>>>(mask, w_proj, out);
}

// round 15
// speedup vs baseline: 1.0116x; 1.0116x over previous
#include <cuda_runtime.h>
#include <cstdint>

#define B_   8
#define CIN  96
#define CMID 48
#define HH   256
#define WW   256
#define H2   128
#define W2   128
#define CO   192

// conv1 output y in fp16: [b][oc][h][w], stored as half2 (adjacent pixels). 50 MB.
__device__ unsigned g_yh[B_ * CMID * HH * WW / 2];
// Pre-packed fp16 weights, LDS.64-pair layout:
// [chunk6][tap9][u4][oc*2+s], pitch 104 words; value = half2 of ic pair
// (ic = chunk*16 + (u + 4s)*2). 6*3744 words.
__device__ unsigned g_wph[6 * 3744];
// Pre-packed, pre-padded fp16 x: [b][icp48][row 258][col 264] half2. ~105 MB.
#define XPR 258
#define XPC 264
__device__ unsigned g_xh[B_ * 48 * XPR * XPC];

__device__ __forceinline__ unsigned pack_h2(float lo, float hi) {
    unsigned r;
    asm("{ .reg .b16 l, h; cvt.rn.f16.f32 l, %1; cvt.rn.f16.f32 h, %2; "
        "mov.b32 %0, {l, h}; }" : "=r"(r) : "f"(lo), "f"(hi));
    return r;
}
__device__ __forceinline__ float2 h2f2(unsigned h) {
    float2 f;
    asm("{ .reg .b16 l, h; mov.b32 {l, h}, %2; "
        "cvt.f32.f16 %0, l; cvt.f32.f16 %1, h; }"
        : "=f"(f.x), "=f"(f.y) : "r"(h));
    return f;
}

__device__ __forceinline__ void mma_f16(float* c,
    unsigned a0, unsigned a1, unsigned a2, unsigned a3,
    unsigned b0, unsigned b1)
{
    asm volatile(
        "mma.sync.aligned.m16n8k16.row.col.f32.f16.f16.f32 "
        "{%0,%1,%2,%3}, {%4,%5,%6,%7}, {%8,%9}, {%0,%1,%2,%3};"
        : "+f"(c[0]), "+f"(c[1]), "+f"(c[2]), "+f"(c[3])
        : "r"(a0), "r"(a1), "r"(a2), "r"(a3), "r"(b0), "r"(b1));
}

__device__ __forceinline__ uint32_t smem_u32(const void* p) {
    uint32_t a;
    asm("{ .reg .u64 t; cvta.to.shared.u64 t, %1; cvt.u32.u64 %0, t; }"
        : "=r"(a) : "l"(p));
    return a;
}
#define CP_ASYNC16(dst, src) \
    asm volatile("cp.async.cg.shared.global [%0], [%1], 16;" \
                 :: "r"(dst), "l"(src))
#define CP_COMMIT() asm volatile("cp.async.commit_group;" ::: "memory")
#define CP_WAIT1()  asm volatile("cp.async.wait_group 1;" ::: "memory")
#define CP_WAIT0()  asm volatile("cp.async.wait_group 0;" ::: "memory")

// ---------------------------------------------------------------------------
// Fused prepass: weights (pair layout) then x relayout.
// ---------------------------------------------------------------------------
#define WN   (6 * 9 * 8 * 48)
#define PX_N (B_ * 48 * XPR * (XPC / 4))

__global__ void prep_kernel(const float* __restrict__ x,
                            const float* __restrict__ w)
{
    int i = blockIdx.x * 256 + threadIdx.x;
    if (i < WN) {
        int chunk = i / 3456;
        int r  = i % 3456;
        int tap = r / 384;
        int r2  = r % 384;
        int icp = r2 / 48;
        int oc  = r2 % 48;
        int ic  = chunk * 16 + icp * 2;
        int u   = icp & 3;
        int s   = icp >> 2;
        g_wph[chunk * 3744 + (tap * 4 + u) * 104 + oc * 2 + s] =
            pack_h2(w[(oc * 96 + ic) * 9 + tap],
                    w[(oc * 96 + ic + 1) * 9 + tap]);
        return;
    }
    i -= WN;
    if (i >= PX_N) return;
    int pc0 = (i % (XPC / 4)) * 4;
    int t   = i / (XPC / 4);
    int pr  = t % XPR;
    int t2  = t / XPR;
    int icp = t2 % 48;
    int b   = t2 / 48;
    int gr  = pr - 1;
    const float* s0 = x + ((size_t)((b * CIN + icp * 2) * HH + gr)) * WW;
    const float* s1 = s0 + (size_t)HH * WW;
    bool rok = ((unsigned)gr < (unsigned)HH);
    unsigned res[4];
    #pragma unroll
    for (int j = 0; j < 4; j++) {
        int ww = pc0 + j - 1;
        bool ok = rok && ((unsigned)ww < (unsigned)WW);
        float f0 = ok ? s0[ww] : 0.f;
        float f1 = ok ? s1[ww] : 0.f;
        res[j] = pack_h2(f0, f1);
    }
    *(uint4*)&g_xh[((size_t)(b * 48 + icp) * XPR + pr) * XPC + pc0] =
        *(uint4*)res;
}

// ---------------------------------------------------------------------------
// conv1 via mma.sync fp16 m16n8k16, cp.async double-buffered.
// v2: 64-col x 4-row tiles (256 px), 3 CTAs/SM, LDS.64 weight pairs.
// Warp: row wid>>1, colbase (wid&1)*32, 2 m-tiles of 16 px.
// ---------------------------------------------------------------------------
#define XS_WORDS (8 * 6 * 68)    // 3264
#define WS_WORDS 3744
#define SMEM_SZ  ((2 * XS_WORDS + 2 * WS_WORDS) * 4)   // 56064

__global__ __launch_bounds__(256, 3) void conv1_mma_kernel()
{
    extern __shared__ unsigned sm[];
    unsigned* xs0 = sm;
    unsigned* ws0 = sm + 2 * XS_WORDS;

    const int tid  = threadIdx.x;
    const int lane = tid & 31;
    const int wid  = tid >> 5;
    const int g    = lane >> 2;
    const int u    = lane & 3;

    const int w0 = blockIdx.x * 64;
    const int h0 = blockIdx.y * 4;
    const int b  = blockIdx.z;

    const int wrow  = wid >> 1;          // 0..3
    const int wcolb = (wid & 1) * 32;    // 0 or 32

    const uint32_t xs_sm = smem_u32(xs0);
    const uint32_t ws_sm = smem_u32(ws0);

    auto issue = [&](int chunk, int buf) {
        // x: icp = wid; 6 rows x 17 uint4 (cols w0-1 .. w0+64 in x space)
        const unsigned* srcp =
            g_xh + ((size_t)(b * 48 + chunk * 8 + wid) * XPR + h0) * XPC + w0;
        uint32_t xd = xs_sm + (buf * XS_WORDS + wid * (6 * 68)) * 4;
        for (int j = lane; j < 102; j += 32) {
            int r = j / 17, q = j - r * 17;
            CP_ASYNC16(xd + (r * 68 + q * 4) * 4,
                       srcp + (size_t)r * XPC + q * 4);
        }
        // w: 936 uint4 straight copy, warp wid owns 117
        const unsigned* wsrc = g_wph + chunk * 3744;
        uint32_t wd = ws_sm + buf * WS_WORDS * 4;
        for (int j = lane; j < 117; j += 32) {
            int k = wid * 117 + j;
            CP_ASYNC16(wd + k * 16, wsrc + k * 4);
        }
    };

    float acc[2][6][4];
    #pragma unroll
    for (int t = 0; t < 2; t++)
        #pragma unroll
        for (int n = 0; n < 6; n++)
            #pragma unroll
            for (int k = 0; k < 4; k++)
                acc[t][n][k] = 0.f;

    issue(0, 0);
    CP_COMMIT();

    for (int chunk = 0; chunk < 6; chunk++) {
        const int buf = chunk & 1;
        if (chunk < 5) {
            issue(chunk + 1, buf ^ 1);
            CP_COMMIT();
            CP_WAIT1();
        } else {
            CP_WAIT0();
        }
        __syncthreads();

        const unsigned* xsb = xs0 + buf * XS_WORDS;
        const unsigned* wsb = ws0 + buf * WS_WORDS;

        #pragma unroll
        for (int tap = 0; tap < 9; tap++) {
            const int kh = tap / 3, kw = tap % 3;
            const int xr = wrow + kh;

            unsigned bf[6][2];
            #pragma unroll
            for (int n = 0; n < 6; n++) {
                uint2 wv = *(const uint2*)
                    &wsb[(tap * 4 + u) * 104 + (n * 8 + g) * 2];
                bf[n][0] = wv.x;    // icp = u      (k pairs 2u, 2u+1)
                bf[n][1] = wv.y;    // icp = u + 4  (k pairs 2u+8, 2u+9)
            }
            #pragma unroll
            for (int t = 0; t < 2; t++) {
                const int colc = wcolb + t * 16 + g + kw;
                unsigned a0 = xsb[(u * 6 + xr) * 68 + colc];
                unsigned a1 = xsb[(u * 6 + xr) * 68 + colc + 8];
                unsigned a2 = xsb[((u + 4) * 6 + xr) * 68 + colc];
                unsigned a3 = xsb[((u + 4) * 6 + xr) * 68 + colc + 8];
                #pragma unroll
                for (int n = 0; n < 6; n++)
                    mma_f16(acc[t][n], a0, a1, a2, a3, bf[n][0], bf[n][1]);
            }
        }
        __syncthreads();
    }

    // ---- store y fp16 half2 (pair lanes g, g^1 = adjacent pixels) ----
    #pragma unroll
    for (int t = 0; t < 2; t++) {
        const int col = wcolb + t * 16 + g;       // pixel col within tile
        const int h   = h0 + wrow;
        const int hc  = (w0 + col) >> 1;          // half2 col (col even on g even)
        #pragma unroll
        for (int n = 0; n < 6; n++) {
            const int oc = n * 8 + 2 * u;
            float q0 = __shfl_xor_sync(0xffffffffu, acc[t][n][0], 4);
            float q1 = __shfl_xor_sync(0xffffffffu, acc[t][n][1], 4);
            float q2 = __shfl_xor_sync(0xffffffffu, acc[t][n][2], 4);
            float q3 = __shfl_xor_sync(0xffffffffu, acc[t][n][3], 4);
            if (!(g & 1)) {
                unsigned* base =
                    g_yh + ((size_t)(b * CMID + oc) * HH + h) * 128 + hc;
                base[0]                       = pack_h2(acc[t][n][0], q0);
                base[(size_t)HH * WW / 2]     = pack_h2(acc[t][n][1], q1);
                base[4]                       = pack_h2(acc[t][n][2], q2);
                base[(size_t)HH * WW / 2 + 4] = pack_h2(acc[t][n][3], q3);
            }
        }
    }
}

// ---------------------------------------------------------------------------
// Kernel B (R12 exact, proven 55us): fused pixel_unshuffle + mask interleave
// + grouped 3x3 conv. CTA: 16 rows x 128 cols, thread 2x4.
// ---------------------------------------------------------------------------
__global__ __launch_bounds__(256) void conv2_kernel(
    const float* __restrict__ mask, const float* __restrict__ wp,
    float* __restrict__ out)
{
    __shared__ __align__(16) float sy[2][18][132];
    __shared__ __align__(16) float smm[2][18][132];
    __shared__ float swp[36];

    const int tid = threadIdx.x;
    const int hb  = blockIdx.x * 16;
    const int gp  = blockIdx.y;     // (c, dy)
    const int b   = blockIdx.z;
    const int c   = gp >> 1;
    const int dy  = gp & 1;
    const int g0  = 4 * c + 2 * dy;

    if (tid < 36) swp[tid] = wp[g0 * 18 + tid];

    #pragma unroll
    for (int it = 0; it < 5; it++) {
        int idx = it * 256 + tid;
        if (idx < 1152) {
            int r  = idx >> 6;
            int q2 = (idx & 63) * 2;
            int gy = 2 * (hb - 1 + r) + dy;
            uint2 yv = make_uint2(0u, 0u);
            float4 mv = make_float4(0.f, 0.f, 0.f, 0.f);
            if ((unsigned)gy < (unsigned)HH) {
                yv = *(const uint2*)&g_yh[((size_t)(b * CMID + c) * HH + gy) * 128 + q2];
                mv = *(const float4*)&mask[((size_t)(b * HH) + gy) * WW + 2 * q2];
            }
            float2 f0 = h2f2(yv.x), f1 = h2f2(yv.y);
            sy[0][r][1 + q2] = f0.x;  sy[1][r][1 + q2] = f0.y;
            sy[0][r][2 + q2] = f1.x;  sy[1][r][2 + q2] = f1.y;
            smm[0][r][1 + q2] = mv.x; smm[1][r][1 + q2] = mv.y;
            smm[0][r][2 + q2] = mv.z; smm[1][r][2 + q2] = mv.w;
        }
    }
    if (tid < 18) {
        sy[0][tid][0] = 0.f;   sy[1][tid][0] = 0.f;
        sy[0][tid][129] = 0.f; sy[1][tid][129] = 0.f;
        smm[0][tid][0] = 0.f;   smm[1][tid][0] = 0.f;
        smm[0][tid][129] = 0.f; smm[1][tid][129] = 0.f;
    }
    __syncthreads();

    const int rr  = tid >> 5;
    const int w0c = (tid & 31) * 4;

    float a[2][2][4];
    #pragma unroll
    for (int o = 0; o < 2; o++)
        #pragma unroll
        for (int gx = 0; gx < 2; gx++)
            #pragma unroll
            for (int p = 0; p < 4; p++)
                a[o][gx][p] = 0.f;

    #pragma unroll
    for (int r = 0; r < 4; r++) {
        const int sr = 2 * rr + r;
        float4 ya0 = *(const float4*)&sy[0][sr][w0c];
        float2 yb0 = *(const float2*)&sy[0][sr][w0c + 4];
        float4 ya1 = *(const float4*)&sy[1][sr][w0c];
        float2 yb1 = *(const float2*)&sy[1][sr][w0c + 4];
        float4 ma0 = *(const float4*)&smm[0][sr][w0c];
        float2 mb0 = *(const float2*)&smm[0][sr][w0c + 4];
        float4 ma1 = *(const float4*)&smm[1][sr][w0c];
        float2 mb1 = *(const float2*)&smm[1][sr][w0c + 4];
        float yv0[6] = {ya0.x, ya0.y, ya0.z, ya0.w, yb0.x, yb0.y};
        float yv1[6] = {ya1.x, ya1.y, ya1.z, ya1.w, yb1.x, yb1.y};
        float mv0[6] = {ma0.x, ma0.y, ma0.z, ma0.w, mb0.x, mb0.y};
        float mv1[6] = {ma1.x, ma1.y, ma1.z, ma1.w, mb1.x, mb1.y};

        #pragma unroll
        for (int orow = 0; orow < 2; orow++) {
            const int kh = r - orow;
            if (kh < 0 || kh > 2) continue;
            #pragma unroll
            for (int kw = 0; kw < 3; kw++) {
                float wy0 = swp[kh * 3 + kw];
                float wm0 = swp[9 + kh * 3 + kw];
                float wy1 = swp[18 + kh * 3 + kw];
                float wm1 = swp[27 + kh * 3 + kw];
                #pragma unroll
                for (int p = 0; p < 4; p++) {
                    a[orow][0][p] = fmaf(wy0, yv0[kw + p], a[orow][0][p]);
                    a[orow][0][p] = fmaf(wm0, mv0[kw + p], a[orow][0][p]);
                    a[orow][1][p] = fmaf(wy1, yv1[kw + p], a[orow][1][p]);
                    a[orow][1][p] = fmaf(wm1, mv1[kw + p], a[orow][1][p]);
                }
            }
        }
    }

    #pragma unroll
    for (int orow = 0; orow < 2; orow++) {
        const int h = hb + 2 * rr + orow;
        *(float4*)&out[((size_t)(b * CO + g0) * H2 + h) * W2 + w0c] =
            make_float4(a[orow][0][0], a[orow][0][1], a[orow][0][2], a[orow][0][3]);
        *(float4*)&out[((size_t)(b * CO + g0 + 1) * H2 + h) * W2 + w0c] =
            make_float4(a[orow][1][0], a[orow][1][1], a[orow][1][2], a[orow][1][3]);
    }
}

// ---------------------------------------------------------------------------
extern "C" void kernel_launch(void* const* d_in, const int* in_sizes, int n_in,
                              void* d_out, int out_size)
{
    const float* x      = (const float*)d_in[0];
    const float* mask   = (const float*)d_in[1];
    const float* w_body = (const float*)d_in[2];
    const float* w_proj = (const float*)d_in[3];
    float* out = (float*)d_out;

    cudaFuncSetAttribute(conv1_mma_kernel,
                         cudaFuncAttributeMaxDynamicSharedMemorySize, SMEM_SZ);

    prep_kernel<<<(WN + PX_N + 255) / 256, 256>>>(x, w_body);

    dim3 g1(WW / 64, HH / 4, B_);       // (4, 64, 8) = 2048 CTAs
    conv1_mma_kernel<<<g1, 256, SMEM_SZ>>>();

    dim3 g2(H2 / 16, 96, B_);           // (8, 96, 8) = 6144 CTAs
    conv2_kernel<<<g2, 256>>>(mask, w_proj, out);
}